// round 3
// baseline (speedup 1.0000x reference)
#include <cuda_runtime.h>
#include <cuda_bf16.h>

#define BB   32
#define TT   1024
#define DD   512
#define HH   512
#define G4   2048
#define NCTA 128

// ---------------- scratch (static device globals; no allocs allowed) --------
__device__ float    g_xw[(size_t)TT * BB * G4];   // [t][b][4H] precomputed x@Wx + bias (256 MB)
__device__ float    g_h[2][HH * BB];              // double-buffered hidden state, [j][b] layout
__device__ unsigned g_bar;                        // grid barrier counter

// ---------------- packed fp32x2 helpers -------------------------------------
__device__ __forceinline__ unsigned long long pack2(float x) {
    unsigned long long r;
    asm("mov.b64 %0, {%1, %1};" : "=l"(r) : "r"(__float_as_uint(x)));
    return r;
}
__device__ __forceinline__ void fma2(unsigned long long& acc, unsigned long long a, unsigned long long b) {
    asm("fma.rn.f32x2 %0, %1, %2, %0;" : "+l"(acc) : "l"(a), "l"(b));
}
__device__ __forceinline__ void add2(unsigned long long& acc, unsigned long long o) {
    asm("add.rn.f32x2 %0, %0, %1;" : "+l"(acc) : "l"(o));
}

__device__ __forceinline__ float fsig(float x) {
    return 1.f / (1.f + __expf(-x));
}
__device__ __forceinline__ float ftanh(float x) {
    // overflow-safe tanh via expf (c can grow over 1024 steps; fast-math tanhf too sloppy)
    float ax = fminf(fabsf(x), 15.f);
    float e  = __expf(2.f * ax);
    float r  = (e - 1.f) / (e + 1.f);
    return copysignf(r, x);
}

// ---------------- reset: barrier counter + h buffer 0 -----------------------
__global__ void reset_kernel() {
    int idx = blockIdx.x * blockDim.x + threadIdx.x;
    if (idx == 0) g_bar = 0u;
    if (idx < HH * BB) g_h[0][idx] = 0.f;
}

// ---------------- kernel 1: XW = X @ Wx + b, stored [t][b][4H] ---------------
// 128x128 tile, 256 threads, 8x8 per-thread register tile, packed f32x2 FMA.
__global__ __launch_bounds__(256) void gemm_xw_kernel(
    const float* __restrict__ X, const float* __restrict__ Wx, const float* __restrict__ bias)
{
    __shared__ float As[16][132];   // transposed A tile [k][m], padded
    __shared__ float Bs[16][128];   // B tile [k][n]

    int tid = threadIdx.x;
    int m0 = blockIdx.y * 128;
    int n0 = blockIdx.x * 128;
    int ty = tid >> 4, tx = tid & 15;

    unsigned long long acc[8][4];
#pragma unroll
    for (int i = 0; i < 8; i++)
#pragma unroll
        for (int j = 0; j < 4; j++) acc[i][j] = 0ull;

    for (int k0 = 0; k0 < DD; k0 += 16) {
#pragma unroll
        for (int i = 0; i < 2; i++) {          // A: 128 rows x 16 k, transpose on store
            int f = tid + 256 * i;
            int r = f >> 2, cs = f & 3;
            float4 v = *(const float4*)&X[(size_t)(m0 + r) * DD + k0 + cs * 4];
            As[cs * 4 + 0][r] = v.x; As[cs * 4 + 1][r] = v.y;
            As[cs * 4 + 2][r] = v.z; As[cs * 4 + 3][r] = v.w;
        }
#pragma unroll
        for (int i = 0; i < 2; i++) {          // B: 16 k x 128 n
            int f = tid + 256 * i;
            int r = f >> 5, cs = f & 31;
            *(float4*)&Bs[r][cs * 4] = *(const float4*)&Wx[(size_t)(k0 + r) * G4 + n0 + cs * 4];
        }
        __syncthreads();
#pragma unroll 4
        for (int kk = 0; kk < 16; kk++) {
            float4 a0 = *(float4*)&As[kk][ty * 8];
            float4 a1 = *(float4*)&As[kk][ty * 8 + 4];
            ulonglong2 w0 = *(ulonglong2*)&Bs[kk][tx * 8];
            ulonglong2 w1 = *(ulonglong2*)&Bs[kk][tx * 8 + 4];
            unsigned long long wp[4] = {w0.x, w0.y, w1.x, w1.y};
            float av[8] = {a0.x, a0.y, a0.z, a0.w, a1.x, a1.y, a1.z, a1.w};
#pragma unroll
            for (int bi = 0; bi < 8; bi++) {
                unsigned long long ad = pack2(av[bi]);
#pragma unroll
                for (int ci = 0; ci < 4; ci++) fma2(acc[bi][ci], ad, wp[ci]);
            }
        }
        __syncthreads();
    }

    float bl[8];
#pragma unroll
    for (int ci = 0; ci < 8; ci++) bl[ci] = bias[n0 + tx * 8 + ci];

#pragma unroll
    for (int bi = 0; bi < 8; bi++) {
        int m = m0 + ty * 8 + bi;
        int bb = m >> 10, t = m & 1023;       // m = b*T + t
        float* dst = &g_xw[((size_t)t * BB + bb) * G4 + n0 + tx * 8];
#pragma unroll
        for (int ci = 0; ci < 4; ci++) {
            unsigned long long u = acc[bi][ci];
            float lo = __uint_as_float((unsigned)u)         + bl[ci * 2];
            float hi = __uint_as_float((unsigned)(u >> 32)) + bl[ci * 2 + 1];
            dst[ci * 2]     = lo;
            dst[ci * 2 + 1] = hi;
        }
    }
}

// ---------------- kernel 2: persistent recurrence ----------------------------
// 128 CTAs x 256 threads, each CTA owns 4 h-columns (16 gate columns) for all 32 batches.
// 114KB smem -> 1 CTA/SM; 128 CTAs <= 148 SMs on B200 => single-wave co-residency,
// so the spin grid-barrier cannot deadlock.
// Per step: z_part = h @ Wh_slice (split-K x32, 8x8 f32x2 tiles) -> warp shuffle
// reduce -> smem reduce -> gate update (c in registers) -> h write -> grid barrier.
__global__ __launch_bounds__(256, 1) void lstm_rec_kernel(
    const float* __restrict__ Wh, float* __restrict__ out)
{
    extern __shared__ float smem[];
    float* wh_s  = smem;                  // [512][16]  32 KB
    float* h_s   = smem + 512 * 16;       // [512][32]  64 KB (k-major: h_s[k][b])
    float* red_s = h_s + 512 * 32;        // [64][64]   16 KB
    float* z_s   = red_s + 64 * 64;       // [512]       2 KB

    int tid = threadIdx.x;
    int j0  = blockIdx.x * 4;

    // load Wh slice: wh_s[k][c], c = gate*4 + jj -> global col gate*512 + j0 + jj
    for (int idx = tid; idx < 512 * 16; idx += 256) {
        int k = idx >> 4, c = idx & 15;
        wh_s[idx] = Wh[(size_t)k * G4 + (c >> 2) * HH + j0 + (c & 3)];
    }

    // GEMM roles: 32 k-chunks x (4 b-tiles x 2 c-tiles)
    int kc = tid >> 3, pos = tid & 7;
    int b0 = (pos >> 1) * 8, c0 = (pos & 1) * 8;
    int kbase = kc * 16;
    int warp = tid >> 5;

    // update role (tid < 128): owns (batch ub, h-col j0+uj); c lives in a register
    int ub = tid >> 2, uj = tid & 3;
    float creg = 0.f;
    float* outp = out + ((size_t)ub * TT) * HH + j0 + uj;

    unsigned bar_target = NCTA;
    __syncthreads();

    for (int t = 0; t < TT; t++) {
        // prefetch this step's x@Wx gate pre-activations early (hides L2/HBM latency)
        float px0 = 0.f, px1 = 0.f, px2 = 0.f, px3 = 0.f;
        if (tid < 128) {
            const float* xr = g_xw + ((size_t)t * BB + ub) * G4 + j0 + uj;
            px0 = __ldg(xr);        px1 = __ldg(xr + 512);
            px2 = __ldg(xr + 1024); px3 = __ldg(xr + 1536);
        }
        // broadcast h (64 KB) from L2 into smem; .cg avoids stale per-SM L1 lines
        {
            const float4* src = (const float4*)g_h[t & 1];
            float4*       dst = (float4*)h_s;
#pragma unroll
            for (int i = 0; i < 16; i++)
                dst[tid + 256 * i] = __ldcg(src + tid + 256 * i);
        }
        __syncthreads();

        unsigned long long acc[8][4];
#pragma unroll
        for (int i = 0; i < 8; i++)
#pragma unroll
            for (int j = 0; j < 4; j++) acc[i][j] = 0ull;

#pragma unroll 4
        for (int kk = 0; kk < 16; kk++) {
            int k = kbase + kk;
            float4 hA = *(float4*)&h_s[k * 32 + b0];
            float4 hB = *(float4*)&h_s[k * 32 + b0 + 4];
            ulonglong2 w0 = *(ulonglong2*)&wh_s[k * 16 + c0];
            ulonglong2 w1 = *(ulonglong2*)&wh_s[k * 16 + c0 + 4];
            unsigned long long wp[4] = {w0.x, w0.y, w1.x, w1.y};
            float hv[8] = {hA.x, hA.y, hA.z, hA.w, hB.x, hB.y, hB.z, hB.w};
#pragma unroll
            for (int bi = 0; bi < 8; bi++) {
                unsigned long long hd = pack2(hv[bi]);
#pragma unroll
                for (int ci = 0; ci < 4; ci++) fma2(acc[bi][ci], hd, wp[ci]);
            }
        }

        // butterfly-reduce the 4 k-chunks that live in one warp (lane bits 3,4)
#pragma unroll
        for (int bi = 0; bi < 8; bi++)
#pragma unroll
            for (int ci = 0; ci < 4; ci++) {
                unsigned long long v = acc[bi][ci];
                unsigned long long o = __shfl_xor_sync(0xffffffffu, v, 8);
                add2(v, o);
                o = __shfl_xor_sync(0xffffffffu, v, 16);
                add2(v, o);
                acc[bi][ci] = v;
            }

        if ((tid & 24) == 0) {   // one lane-group per (warp,pos) stores its 64 partials
            float* rb = red_s + (warp * 8 + pos) * 64;
#pragma unroll
            for (int bi = 0; bi < 8; bi++)
#pragma unroll
                for (int ci = 0; ci < 4; ci++)
                    *(unsigned long long*)&rb[bi * 8 + ci * 2] = acc[bi][ci];
        }
        __syncthreads();

        // final reduce across the 8 warps: 512 outputs, 2 per thread
#pragma unroll
        for (int r = 0; r < 2; r++) {
            int o = tid + 256 * r;
            int b = o >> 4, c = o & 15;
            int p = ((b >> 3) << 1) | (c >> 3);
            int e = ((b & 7) << 3) | (c & 7);
            float s = 0.f;
#pragma unroll
            for (int w = 0; w < 8; w++) s += red_s[(w * 8 + p) * 64 + e];
            z_s[o] = s;
        }
        __syncthreads();

        // gate update: z = z_s + x@Wx; c stays in creg across all 1024 steps
        if (tid < 128) {
            int zb = ub * 16 + uj;
            float zi = z_s[zb]      + px0;
            float zf = z_s[zb + 4]  + px1;
            float zg = z_s[zb + 8]  + px2;
            float zo = z_s[zb + 12] + px3;
            float ig = fsig(zi);
            float fg = fsig(zf);
            float gg = ftanh(zg);
            float og = fsig(zo);
            float cn = fg * creg + ig * gg;
            creg = cn;
            float hn = og * ftanh(cn);
            g_h[(t + 1) & 1][(j0 + uj) * 32 + ub] = hn;   // next step's h buffer
            outp[(size_t)t * HH] = hn;                     // outputs[b][t][j]
        }
        __syncthreads();

        // grid barrier: red.release arrival (no-return, cheap) + ld.acquire spin
        if (tid == 0) {
            __threadfence();
            asm volatile("red.release.gpu.global.add.u32 [%0], %1;"
                         :: "l"(&g_bar), "r"(1u) : "memory");
            unsigned v;
            do {
                asm volatile("ld.acquire.gpu.global.u32 %0, [%1];"
                             : "=r"(v) : "l"(&g_bar) : "memory");
            } while (v < bar_target);
        }
        bar_target += NCTA;
        __syncthreads();
    }
}

// ---------------- kernel 3: gather final states ------------------------------
// Reference declares lengths int64, but JAX without x64 silently makes int32.
// Sniff the data: any int64-view value outside [0, T] => int32 layout.
// Detection reads only the first 128 bytes (valid under both layouts).
__global__ void gather_final_kernel(const int* __restrict__ lenraw, float* __restrict__ out) {
    __shared__ int is32;
    if (threadIdx.x == 0) {
        const long long* l64 = (const long long*)lenraw;
        int bad = 0;
        for (int b = 0; b < 16; b++) {
            long long v = l64[b];
            if (v < 0 || v > (long long)TT) bad = 1;
        }
        is32 = bad;
    }
    __syncthreads();
    int idx = blockIdx.x * blockDim.x + threadIdx.x;
    if (idx >= BB * HH) return;
    int b = idx >> 9, j = idx & 511;
    long long len = is32 ? (long long)lenraw[b] : ((const long long*)lenraw)[b];
    long long tt = len > 0 ? len - 1 : 0;
    out[(size_t)BB * TT * HH + idx] = out[((size_t)b * TT + tt) * HH + j];
}

// ---------------- launch ------------------------------------------------------
extern "C" void kernel_launch(void* const* d_in, const int* in_sizes, int n_in,
                              void* d_out, int out_size) {
    const float* X    = (const float*)d_in[0];
    const int*   lenr = (const int*)  d_in[1];
    const float* Wx   = (const float*)d_in[2];
    const float* Wh   = (const float*)d_in[3];
    const float* bias = (const float*)d_in[4];
    float* out = (float*)d_out;

    cudaFuncSetAttribute(lstm_rec_kernel,
                         cudaFuncAttributeMaxDynamicSharedMemorySize, 116736);
    cudaFuncSetAttribute(lstm_rec_kernel,
                         cudaFuncAttributePreferredSharedMemoryCarveout, 100);

    reset_kernel<<<64, 256>>>();
    gemm_xw_kernel<<<dim3(16, 256), 256>>>(X, Wx, bias);
    lstm_rec_kernel<<<NCTA, 256, 116736>>>(Wh, out);
    gather_final_kernel<<<64, 256>>>(lenr, out);
}

// round 4
// speedup vs baseline: 1.0919x; 1.0919x over previous
#include <cuda_runtime.h>
#include <cuda_bf16.h>

#define BB   32
#define TT   1024
#define DD   512
#define HH   512
#define G4   2048
#define NCTA 128

// ---------------- scratch (static device globals; no allocs allowed) --------
__device__ float    g_xw[(size_t)TT * BB * G4];   // [t][b][4H] precomputed x@Wx + bias
__device__ float    g_h[2][HH * BB];              // double-buffered hidden state, [j][b] layout
__device__ unsigned g_bar;                        // grid barrier counter

// ---------------- packed fp32x2 helpers -------------------------------------
__device__ __forceinline__ unsigned long long pack2(float x) {
    unsigned long long r;
    asm("mov.b64 %0, {%1, %1};" : "=l"(r) : "r"(__float_as_uint(x)));
    return r;
}
__device__ __forceinline__ void fma2(unsigned long long& acc, unsigned long long a, unsigned long long b) {
    asm("fma.rn.f32x2 %0, %1, %2, %0;" : "+l"(acc) : "l"(a), "l"(b));
}
__device__ __forceinline__ void add2(unsigned long long& acc, unsigned long long o) {
    asm("add.rn.f32x2 %0, %0, %1;" : "+l"(acc) : "l"(o));
}

__device__ __forceinline__ float fsig(float x) {
    return 1.f / (1.f + __expf(-x));
}
__device__ __forceinline__ float ftanh(float x) {
    float ax = fminf(fabsf(x), 15.f);
    float e  = __expf(2.f * ax);
    float r  = (e - 1.f) / (e + 1.f);
    return copysignf(r, x);
}

// ---------------- profiling pad (aligns ncu -s 5 onto lstm_rec) --------------
__global__ void pad_kernel() {}

// ---------------- reset: barrier counter + h buffer 0 -----------------------
__global__ void reset_kernel() {
    int idx = blockIdx.x * blockDim.x + threadIdx.x;
    if (idx == 0) g_bar = 0u;
    if (idx < HH * BB) g_h[0][idx] = 0.f;
}

// ---------------- kernel 1: XW = X @ Wx + b, stored [t][b][4H] ---------------
// 128x128 tile, 256 threads, 8x8 register tile, f32x2 FMA.
// Bs columns swizzled (cs ^= (cs>>3)&3 on 16B units) -> conflict-free 2-phase reads.
__global__ __launch_bounds__(256) void gemm_xw_kernel(
    const float* __restrict__ X, const float* __restrict__ Wx, const float* __restrict__ bias)
{
    __shared__ float As[16][132];   // transposed A tile [k][m], padded
    __shared__ float Bs[16][128];   // B tile [k][n], 16B-unit swizzled

    int tid = threadIdx.x;
    int m0 = blockIdx.y * 128;
    int n0 = blockIdx.x * 128;
    int ty = tid >> 4, tx = tid & 15;

    // swizzled read units for this thread's two B ulonglong2 loads
    int u0 = tx * 2;
    int s0 = u0 ^ ((u0 >> 3) & 3);
    int u1 = u0 + 1;
    int s1 = u1 ^ ((u1 >> 3) & 3);

    unsigned long long acc[8][4];
#pragma unroll
    for (int i = 0; i < 8; i++)
#pragma unroll
        for (int j = 0; j < 4; j++) acc[i][j] = 0ull;

    for (int k0 = 0; k0 < DD; k0 += 16) {
#pragma unroll
        for (int i = 0; i < 2; i++) {          // A: 128 rows x 16 k, transpose on store
            int f = tid + 256 * i;
            int r = f >> 2, cs = f & 3;
            float4 v = *(const float4*)&X[(size_t)(m0 + r) * DD + k0 + cs * 4];
            As[cs * 4 + 0][r] = v.x; As[cs * 4 + 1][r] = v.y;
            As[cs * 4 + 2][r] = v.z; As[cs * 4 + 3][r] = v.w;
        }
#pragma unroll
        for (int i = 0; i < 2; i++) {          // B: 16 k x 128 n, swizzled on store
            int f = tid + 256 * i;
            int r = f >> 5, cs = f & 31;
            int csw = cs ^ ((cs >> 3) & 3);
            *(float4*)&Bs[r][csw * 4] = *(const float4*)&Wx[(size_t)(k0 + r) * G4 + n0 + cs * 4];
        }
        __syncthreads();
#pragma unroll 4
        for (int kk = 0; kk < 16; kk++) {
            float4 a0 = *(float4*)&As[kk][ty * 8];
            float4 a1 = *(float4*)&As[kk][ty * 8 + 4];
            ulonglong2 w0 = *(ulonglong2*)&Bs[kk][s0 * 4];
            ulonglong2 w1 = *(ulonglong2*)&Bs[kk][s1 * 4];
            unsigned long long wp[4] = {w0.x, w0.y, w1.x, w1.y};
            float av[8] = {a0.x, a0.y, a0.z, a0.w, a1.x, a1.y, a1.z, a1.w};
#pragma unroll
            for (int bi = 0; bi < 8; bi++) {
                unsigned long long ad = pack2(av[bi]);
#pragma unroll
                for (int ci = 0; ci < 4; ci++) fma2(acc[bi][ci], ad, wp[ci]);
            }
        }
        __syncthreads();
    }

    float bl[8];
#pragma unroll
    for (int ci = 0; ci < 8; ci++) bl[ci] = bias[n0 + tx * 8 + ci];

#pragma unroll
    for (int bi = 0; bi < 8; bi++) {
        int m = m0 + ty * 8 + bi;
        int bb = m >> 10, t = m & 1023;       // m = b*T + t
        float* dst = &g_xw[((size_t)t * BB + bb) * G4 + n0 + tx * 8];
#pragma unroll
        for (int ci = 0; ci < 4; ci++) {
            unsigned long long u = acc[bi][ci];
            float lo = __uint_as_float((unsigned)u)         + bl[ci * 2];
            float hi = __uint_as_float((unsigned)(u >> 32)) + bl[ci * 2 + 1];
            dst[ci * 2]     = lo;
            dst[ci * 2 + 1] = hi;
        }
    }
}

// ---------------- kernel 2: persistent recurrence ----------------------------
// 128 CTAs x 256 threads; 114KB smem -> 1 CTA/SM; single-wave => spin barrier safe.
// Per step: per-warp cp.async h slice (2 pipelined halves, swizzled units) ->
// f32x2 GEMM (swizzled conflict-free LDS) -> butterfly -> smem reduce ->
// gate update (c in regs) -> h write -> grid barrier.
__global__ __launch_bounds__(256, 1) void lstm_rec_kernel(
    const float* __restrict__ Wh, float* __restrict__ out)
{
    extern __shared__ float smem[];
    float* wh_s  = smem;                  // [512][16]  32 KB, 16B-unit swizzled
    float* h_s   = smem + 512 * 16;       // [512][32]  64 KB (k-major, swizzled)
    float* red_s = h_s + 512 * 32;        // [64][64]   16 KB
    float* z_s   = red_s + 64 * 64;       // [512]       2 KB

    int tid = threadIdx.x;
    int j0  = blockIdx.x * 4;

    // load Wh slice with swizzle: row k, unit cu -> cu ^ ((k>>3)&3)
    for (int idx = tid; idx < 512 * 16; idx += 256) {
        int k = idx >> 4, c = idx & 15;
        int cu  = c >> 2;
        int csw = cu ^ ((k >> 3) & 3);
        wh_s[k * 16 + csw * 4 + (c & 3)] = Wh[(size_t)k * G4 + (c >> 2) * HH + j0 + (c & 3)];
    }

    // GEMM roles: warp w owns k in [64w, 64w+64); lane-group g = (tid>>3)&3,
    // pos = tid&7 -> 8x8 output tile. Thread k set: {32h + 8g + j : h<2, j<8}.
    int w    = tid >> 5;
    int g    = (tid >> 3) & 3;
    int pos  = tid & 7;
    int b0   = (pos >> 1) * 8, c0 = (pos & 1) * 8;
    int lane = tid & 31;
    int b16  = (pos >> 1) * 2;
    int cu0  = (pos & 1) * 2;

    // precomputed swizzled read offsets (within-warp units for h, within-row for wh)
    int hu_a = b16 ^ g;            // first float4 unit offset in k-row
    int hu_b = (b16 + 1) ^ g;      // second
    int wu_a = cu0 ^ g;
    int wu_b = (cu0 + 1) ^ g;

    float* hw = h_s + w * 2048;    // warp's 8KB slice (floats)
    unsigned hs_base = (unsigned)__cvta_generic_to_shared(h_s) + w * 8192;

    // update role (tid < 128): owns (batch ub, h-col j0+uj)
    int ub = tid >> 2, uj = tid & 3;
    float creg = 0.f;
    float* outp = out + ((size_t)ub * TT) * HH + j0 + uj;

    unsigned bar_target = NCTA;
    __syncthreads();

    for (int t = 0; t < TT; t++) {
        // prefetch this step's x@Wx pre-activations (consumed ~5k cyc later)
        float px0 = 0.f, px1 = 0.f, px2 = 0.f, px3 = 0.f;
        if (tid < 128) {
            const float* xr = g_xw + ((size_t)t * BB + ub) * G4 + j0 + uj;
            px0 = __ldg(xr);        px1 = __ldg(xr + 512);
            px2 = __ldg(xr + 1024); px3 = __ldg(xr + 1536);
        }

        // per-warp pipelined h broadcast: two 4KB halves via cp.async.cg (L1 bypass)
        {
            const float* src_base = g_h[t & 1] + w * 2048;
#pragma unroll
            for (int hh = 0; hh < 2; hh++) {
#pragma unroll
                for (int i = 0; i < 8; i++) {
                    int un  = hh * 256 + i * 32 + lane;
                    int gg  = (un >> 6) & 3;
                    int usw = (un & ~7) | ((un & 7) ^ gg);
                    asm volatile("cp.async.cg.shared.global [%0], [%1], 16;"
                                 :: "r"(hs_base + usw * 16), "l"(src_base + un * 4)
                                 : "memory");
                }
                asm volatile("cp.async.commit_group;");
            }
        }

        unsigned long long acc[8][4];
#pragma unroll
        for (int i = 0; i < 8; i++)
#pragma unroll
            for (int j = 0; j < 4; j++) acc[i][j] = 0ull;

#pragma unroll
        for (int hh = 0; hh < 2; hh++) {
            if (hh == 0) { asm volatile("cp.async.wait_group 1;" ::: "memory"); }
            else         { asm volatile("cp.async.wait_group 0;" ::: "memory"); }
            __syncwarp();
#pragma unroll 4
            for (int j = 0; j < 8; j++) {
                int kl = hh * 32 + 8 * g + j;          // k_local within warp slice
                float4 hA = *(float4*)&hw[(kl * 8 + hu_a) * 4];
                float4 hB = *(float4*)&hw[(kl * 8 + hu_b) * 4];
                const float* wrow = &wh_s[(64 * w + kl) * 16];
                ulonglong2 w0 = *(ulonglong2*)&wrow[wu_a * 4];
                ulonglong2 w1 = *(ulonglong2*)&wrow[wu_b * 4];
                unsigned long long wp[4] = {w0.x, w0.y, w1.x, w1.y};
                float hv[8] = {hA.x, hA.y, hA.z, hA.w, hB.x, hB.y, hB.z, hB.w};
#pragma unroll
                for (int bi = 0; bi < 8; bi++) {
                    unsigned long long hd = pack2(hv[bi]);
#pragma unroll
                    for (int ci = 0; ci < 4; ci++) fma2(acc[bi][ci], hd, wp[ci]);
                }
            }
        }

        // butterfly-reduce the 4 lane-groups (lane bits 3,4) within each warp
#pragma unroll
        for (int bi = 0; bi < 8; bi++)
#pragma unroll
            for (int ci = 0; ci < 4; ci++) {
                unsigned long long v = acc[bi][ci];
                unsigned long long o = __shfl_xor_sync(0xffffffffu, v, 8);
                add2(v, o);
                o = __shfl_xor_sync(0xffffffffu, v, 16);
                add2(v, o);
                acc[bi][ci] = v;
            }

        if ((tid & 24) == 0) {   // one lane-group per (warp,pos) stores 64 partials
            float* rb = red_s + (w * 8 + pos) * 64;
#pragma unroll
            for (int bi = 0; bi < 8; bi++)
#pragma unroll
                for (int ci = 0; ci < 4; ci++)
                    *(unsigned long long*)&rb[bi * 8 + ci * 2] = acc[bi][ci];
        }
        __syncthreads();

        // final reduce across the 8 warps: 512 outputs, 2 per thread
#pragma unroll
        for (int r = 0; r < 2; r++) {
            int o = tid + 256 * r;
            int b = o >> 4, c = o & 15;
            int p = ((b >> 3) << 1) | (c >> 3);
            int e = ((b & 7) << 3) | (c & 7);
            float s = 0.f;
#pragma unroll
            for (int ww = 0; ww < 8; ww++) s += red_s[(ww * 8 + p) * 64 + e];
            z_s[o] = s;
        }
        __syncthreads();

        // gate update: z = z_s + x@Wx; c stays in creg across all 1024 steps
        if (tid < 128) {
            int zb = ub * 16 + uj;
            float zi = z_s[zb]      + px0;
            float zf = z_s[zb + 4]  + px1;
            float zg = z_s[zb + 8]  + px2;
            float zo = z_s[zb + 12] + px3;
            float ig = fsig(zi);
            float fg = fsig(zf);
            float gg = ftanh(zg);
            float og = fsig(zo);
            float cn = fg * creg + ig * gg;
            creg = cn;
            float hn = og * ftanh(cn);
            g_h[(t + 1) & 1][(j0 + uj) * 32 + ub] = hn;   // next step's h buffer
            outp[(size_t)t * HH] = hn;                     // outputs[b][t][j]
        }
        __syncthreads();

        // grid barrier: red.release arrival + ld.acquire spin (1 thread/CTA)
        if (tid == 0) {
            __threadfence();
            asm volatile("red.release.gpu.global.add.u32 [%0], %1;"
                         :: "l"(&g_bar), "r"(1u) : "memory");
            unsigned v;
            do {
                asm volatile("ld.acquire.gpu.global.u32 %0, [%1];"
                             : "=r"(v) : "l"(&g_bar) : "memory");
            } while (v < bar_target);
        }
        bar_target += NCTA;
        __syncthreads();
    }
}

// ---------------- kernel 3: gather final states ------------------------------
// lengths may be int64 (reference) or int32 (JAX w/o x64). Sniff the data:
// any int64-view value outside [0, T] => int32 layout. Reads 128 valid bytes.
__global__ void gather_final_kernel(const int* __restrict__ lenraw, float* __restrict__ out) {
    __shared__ int is32;
    if (threadIdx.x == 0) {
        const long long* l64 = (const long long*)lenraw;
        int bad = 0;
        for (int b = 0; b < 16; b++) {
            long long v = l64[b];
            if (v < 0 || v > (long long)TT) bad = 1;
        }
        is32 = bad;
    }
    __syncthreads();
    int idx = blockIdx.x * blockDim.x + threadIdx.x;
    if (idx >= BB * HH) return;
    int b = idx >> 9, j = idx & 511;
    long long len = is32 ? (long long)lenraw[b] : ((const long long*)lenraw)[b];
    long long tt = len > 0 ? len - 1 : 0;
    out[(size_t)BB * TT * HH + idx] = out[((size_t)b * TT + tt) * HH + j];
}

// ---------------- launch ------------------------------------------------------
extern "C" void kernel_launch(void* const* d_in, const int* in_sizes, int n_in,
                              void* d_out, int out_size) {
    const float* X    = (const float*)d_in[0];
    const int*   lenr = (const int*)  d_in[1];
    const float* Wx   = (const float*)d_in[2];
    const float* Wh   = (const float*)d_in[3];
    const float* bias = (const float*)d_in[4];
    float* out = (float*)d_out;

    cudaFuncSetAttribute(lstm_rec_kernel,
                         cudaFuncAttributeMaxDynamicSharedMemorySize, 116736);
    cudaFuncSetAttribute(lstm_rec_kernel,
                         cudaFuncAttributePreferredSharedMemoryCarveout, 100);

    pad_kernel<<<1, 32>>>();                       // profile alignment only
    reset_kernel<<<64, 256>>>();
    gemm_xw_kernel<<<dim3(16, 256), 256>>>(X, Wx, bias);
    lstm_rec_kernel<<<NCTA, 256, 116736>>>(Wh, out);
    gather_final_kernel<<<64, 256>>>(lenr, out);
}